// round 1
// baseline (speedup 1.0000x reference)
#include <cuda_runtime.h>
#include <cuda_bf16.h>
#include <cstdint>

// Scratch (static device memory — allowed; no cudaMalloc anywhere)
__device__ float g_q [4096u * 1024u];   // Q  = x @ w_q       [4096,1024]
__device__ float g_kv[4096u * 2048u];   // KV = x @ w_vk      [4096,2048] (K cols 0:1024, V cols 1024:2048)
__device__ float g_ao[4096u * 1024u];   // attention output   [4096,1024]

// ---------------------------------------------------------------------------
// Classic fp32 SGEMM: C[M,N] = A[M,K] @ B[K,N], all row-major.
// 128x128 block tile, BK=16, 256 threads, 8x8 register tile per thread.
// M,N multiples of 128; K multiple of 16 (true for all 3 calls).
// ---------------------------------------------------------------------------
__global__ void __launch_bounds__(256, 2)
sgemm_kernel(const float* __restrict__ A, const float* __restrict__ B,
             float* __restrict__ C, int M, int N, int K) {
    __shared__ float As[16][132];   // transposed A tile: As[k][m], padded
    __shared__ float Bs[16][128];   // B tile: Bs[k][n]

    const int tid = threadIdx.x;
    const int bm  = blockIdx.y * 128;
    const int bn  = blockIdx.x * 128;
    const int tx  = tid & 15;       // n-dir thread coord
    const int ty  = tid >> 4;       // m-dir thread coord
    const int arow = tid >> 2;          // 0..63
    const int acol = (tid & 3) << 2;    // 0,4,8,12
    const int brow = tid >> 5;          // 0..7
    const int bcol = (tid & 31) << 2;   // 0..124

    float acc[8][8];
#pragma unroll
    for (int i = 0; i < 8; i++)
#pragma unroll
        for (int j = 0; j < 8; j++) acc[i][j] = 0.f;

    const float* Ab = A + (size_t)bm * K;
    const float* Bb = B + bn;

    for (int k0 = 0; k0 < K; k0 += 16) {
#pragma unroll
        for (int p = 0; p < 2; p++) {
            int r = arow + p * 64;
            float4 v = *reinterpret_cast<const float4*>(Ab + (size_t)r * K + k0 + acol);
            As[acol + 0][r] = v.x;
            As[acol + 1][r] = v.y;
            As[acol + 2][r] = v.z;
            As[acol + 3][r] = v.w;
        }
#pragma unroll
        for (int p = 0; p < 2; p++) {
            int r = brow + p * 8;
            *reinterpret_cast<float4*>(&Bs[r][bcol]) =
                *reinterpret_cast<const float4*>(Bb + (size_t)(k0 + r) * N + bcol);
        }
        __syncthreads();

#pragma unroll
        for (int kk = 0; kk < 16; kk++) {
            float ra[8], rb[8];
            *reinterpret_cast<float4*>(&ra[0]) = *reinterpret_cast<const float4*>(&As[kk][ty * 8 + 0]);
            *reinterpret_cast<float4*>(&ra[4]) = *reinterpret_cast<const float4*>(&As[kk][ty * 8 + 4]);
            *reinterpret_cast<float4*>(&rb[0]) = *reinterpret_cast<const float4*>(&Bs[kk][tx * 8 + 0]);
            *reinterpret_cast<float4*>(&rb[4]) = *reinterpret_cast<const float4*>(&Bs[kk][tx * 8 + 4]);
#pragma unroll
            for (int i = 0; i < 8; i++)
#pragma unroll
                for (int j = 0; j < 8; j++) acc[i][j] += ra[i] * rb[j];
        }
        __syncthreads();
    }

    float* Cb = C + (size_t)(bm + ty * 8) * N + bn + tx * 8;
#pragma unroll
    for (int i = 0; i < 8; i++) {
#pragma unroll
        for (int j = 0; j < 8; j += 4) {
            float4 v = make_float4(acc[i][j], acc[i][j + 1], acc[i][j + 2], acc[i][j + 3]);
            *reinterpret_cast<float4*>(Cb + (size_t)i * N + j) = v;
        }
    }
}

// ---------------------------------------------------------------------------
// Flash attention, fp32. One block handles 64 query rows of one (b,h).
// 256 threads: thread (row = tid>>2, quad = tid&3).
//   - q row (64 floats) cached in registers (4x redundant per row)
//   - per KV tile (64 keys): S phase (each thread: its row x 16 interleaved j),
//     online softmax with quad shuffles, P staged through reused K smem,
//     PV phase (each thread: its row x 16 interleaved d).
// NOTE: reference multiplies dots by sqrt(d)=8.0 (not divide).
// ---------------------------------------------------------------------------
__global__ void __launch_bounds__(256, 2)
flash_kernel(const float* __restrict__ Q, const float* __restrict__ KV,
             float* __restrict__ O) {
    __shared__ float Ks[64 * 68];   // K tile (stride 68); reused as P tile
    __shared__ float Vs[64 * 64];   // V tile (stride 64)

    const int b    = blockIdx.z;
    const int h    = blockIdx.y;
    const int tid  = threadIdx.x;
    const int row  = tid >> 2;      // 0..63
    const int quad = tid & 3;       // 0..3
    const int qbase = blockIdx.x * 64;

    // load q row into registers
    const float* Qrow = Q + ((size_t)(b * 2048 + qbase + row)) * 1024 + h * 64;
    float q[64];
#pragma unroll
    for (int d = 0; d < 64; d += 4) {
        float4 v = *reinterpret_cast<const float4*>(Qrow + d);
        q[d] = v.x; q[d + 1] = v.y; q[d + 2] = v.z; q[d + 3] = v.w;
    }

    float acc[16];
#pragma unroll
    for (int i = 0; i < 16; i++) acc[i] = 0.f;
    float m = -1e30f, l = 0.f;

    const float* Kb = KV + (size_t)b * 2048 * 2048 + h * 64;          // k rows, stride 2048
    const float* Vb = Kb + 1024;                                      // v is second half of kv

    for (int j0 = 0; j0 < 2048; j0 += 64) {
        // ---- load K and V tiles (coalesced float4) ----
#pragma unroll
        for (int t = 0; t < 4; t++) {
            int idx = tid + t * 256;          // 0..1023 covers 64x16 float4
            int r = idx >> 4;
            int c = (idx & 15) << 2;
            float4 k4 = *reinterpret_cast<const float4*>(Kb + (size_t)(j0 + r) * 2048 + c);
            float* ks = &Ks[r * 68 + c];
            ks[0] = k4.x; ks[1] = k4.y; ks[2] = k4.z; ks[3] = k4.w;
            float4 v4 = *reinterpret_cast<const float4*>(Vb + (size_t)(j0 + r) * 2048 + c);
            *reinterpret_cast<float4*>(&Vs[r * 64 + c]) = v4;
        }
        __syncthreads();

        // ---- S = q . k^T * 8, thread owns j = 4*jj + quad ----
        float s[16];
#pragma unroll
        for (int jj = 0; jj < 16; jj++) {
            int j = (jj << 2) | quad;
            const float4* kr = reinterpret_cast<const float4*>(&Ks[j * 68]);
            float dot = 0.f;
#pragma unroll
            for (int d4 = 0; d4 < 16; d4++) {
                float4 k4 = kr[d4];
                dot += q[d4 * 4 + 0] * k4.x + q[d4 * 4 + 1] * k4.y
                     + q[d4 * 4 + 2] * k4.z + q[d4 * 4 + 3] * k4.w;
            }
            s[jj] = dot * 8.0f;   // SCALE = sqrt(64), MULTIPLY (faithful)
        }

        // ---- online softmax (row split over 4 quad lanes) ----
        float tmax = s[0];
#pragma unroll
        for (int jj = 1; jj < 16; jj++) tmax = fmaxf(tmax, s[jj]);
        tmax = fmaxf(tmax, __shfl_xor_sync(0xffffffffu, tmax, 1));
        tmax = fmaxf(tmax, __shfl_xor_sync(0xffffffffu, tmax, 2));
        float mnew = fmaxf(m, tmax);
        float corr = __expf(m - mnew);
        float psum = 0.f;
#pragma unroll
        for (int jj = 0; jj < 16; jj++) {
            float p = __expf(s[jj] - mnew);
            s[jj] = p;
            psum += p;
        }
        psum += __shfl_xor_sync(0xffffffffu, psum, 1);
        psum += __shfl_xor_sync(0xffffffffu, psum, 2);
        l = l * corr + psum;
        m = mnew;
#pragma unroll
        for (int i = 0; i < 16; i++) acc[i] *= corr;

        __syncthreads();   // all lanes done reading Ks
        // ---- stage P into reused Ks buffer: Ps[row][j], stride 68 ----
#pragma unroll
        for (int jj = 0; jj < 16; jj++) Ks[row * 68 + ((jj << 2) | quad)] = s[jj];
        __syncthreads();

        // ---- PV: acc[dd] over d = 4*dd + quad ----
        const float* Pr = &Ks[row * 68];
#pragma unroll 8
        for (int j = 0; j < 64; j++) {
            float pj = Pr[j];
            const float* vr = &Vs[j * 64 + quad];
#pragma unroll
            for (int dd = 0; dd < 16; dd++) acc[dd] += pj * vr[dd * 4];
        }
        __syncthreads();   // before next tile overwrites Ks/Vs
    }

    float inv = 1.0f / l;
    float* Or = O + ((size_t)(b * 2048 + qbase + row)) * 1024 + h * 64 + quad;
#pragma unroll
    for (int dd = 0; dd < 16; dd++) Or[dd * 4] = acc[dd] * inv;
}

// ---------------------------------------------------------------------------
extern "C" void kernel_launch(void* const* d_in, const int* in_sizes, int n_in,
                              void* d_out, int out_size) {
    const float* x     = (const float*)d_in[0];   // [2,2048,1024]
    const float* w_q   = (const float*)d_in[1];   // [1024,1024]
    const float* w_vk  = (const float*)d_in[2];   // [1024,2048]
    const float* w_out = (const float*)d_in[3];   // [1024,1024]
    float* out = (float*)d_out;                   // [2,2048,1024]

    float *q, *kv, *ao;
    cudaGetSymbolAddress((void**)&q,  g_q);
    cudaGetSymbolAddress((void**)&kv, g_kv);
    cudaGetSymbolAddress((void**)&ao, g_ao);

    // Q = x @ w_q            (4096 x 1024 x 1024)
    sgemm_kernel<<<dim3(1024 / 128, 4096 / 128), 256>>>(x, w_q, q, 4096, 1024, 1024);
    // KV = x @ w_vk          (4096 x 2048 x 1024)
    sgemm_kernel<<<dim3(2048 / 128, 4096 / 128), 256>>>(x, w_vk, kv, 4096, 2048, 1024);
    // attention              (32 q-tiles x 16 heads x 2 batch)
    flash_kernel<<<dim3(32, 16, 2), 256>>>(q, kv, ao);
    // out = ao @ w_out       (4096 x 1024 x 1024)
    sgemm_kernel<<<dim3(1024 / 128, 4096 / 128), 256>>>(ao, w_out, out, 4096, 1024, 1024);
}

// round 3
// speedup vs baseline: 3.6145x; 3.6145x over previous
#include <cuda_runtime.h>
#include <cuda_bf16.h>
#include <cstdint>

// Scratch (static device memory — no cudaMalloc anywhere)
__device__ float g_q [4096u * 1024u];   // Q  = x @ w_q       [4096,1024]
__device__ float g_kv[4096u * 2048u];   // KV = x @ w_vk      [4096,2048]
__device__ float g_ao[4096u * 1024u];   // attention output   [4096,1024]

// ---------------------------------------------------------------------------
// helpers
// ---------------------------------------------------------------------------
__device__ __forceinline__ uint32_t f2tf32(float f) {
    uint32_t u;
    asm("cvt.rna.tf32.f32 %0, %1;" : "=r"(u) : "f"(f));
    return u;
}
// split x into (hi, lo) tf32 pair: x ≈ hi + lo
__device__ __forceinline__ void tf32_split(float x, uint32_t& hi, uint32_t& lo) {
    hi = f2tf32(x);
    lo = f2tf32(x - __uint_as_float(hi));
}

// C += A * B  with m16n8k8 tf32 MMA (layouts validated in round 2).
__device__ __forceinline__ void mma_tf32(float c[4], const uint32_t a[4], const uint32_t b[2]) {
    asm volatile(
        "mma.sync.aligned.m16n8k8.row.col.f32.tf32.tf32.f32 "
        "{%0,%1,%2,%3}, {%4,%5,%6,%7}, {%8,%9}, {%0,%1,%2,%3};\n"
        : "+f"(c[0]), "+f"(c[1]), "+f"(c[2]), "+f"(c[3])
        : "r"(a[0]), "r"(a[1]), "r"(a[2]), "r"(a[3]), "r"(b[0]), "r"(b[1]));
}
// 3xTF32: c += (ah+al)*(bh+bl) dropping al*bl
__device__ __forceinline__ void mma3(float c[4], const uint32_t ah[4], const uint32_t al[4],
                                     const uint32_t bh[2], const uint32_t bl[2]) {
    mma_tf32(c, ah, bl);
    mma_tf32(c, al, bh);
    mma_tf32(c, ah, bh);
}

// ---------------------------------------------------------------------------
// 3xTF32 MMA GEMM: C[M,N] = A[M,K] @ B[K,N], row-major fp32 in/out.
// Block 128x128, BK=32, 256 threads = 8 warps (2m x 4n); warp tile 64x32.
// Dynamic smem: As hi/lo [128][36], Bs hi/lo [32][136].
// ---------------------------------------------------------------------------
#define GEMM_AS (128 * 36)
#define GEMM_BS (32 * 136)
#define GEMM_SMEM ((2 * (GEMM_AS + GEMM_BS)) * 4)

__global__ void __launch_bounds__(256, 2)
gemm_3xtf32_kernel(const float* __restrict__ A, const float* __restrict__ B,
                   float* __restrict__ C, int M, int N, int K) {
    extern __shared__ uint32_t sm[];
    uint32_t* Ah = sm;
    uint32_t* Al = sm + GEMM_AS;
    uint32_t* Bh = sm + 2 * GEMM_AS;
    uint32_t* Bl = sm + 2 * GEMM_AS + GEMM_BS;

    const int tid  = threadIdx.x;
    const int lane = tid & 31;
    const int warp = tid >> 5;
    const int g = lane >> 2;
    const int t = lane & 3;
    const int wm = warp >> 2;   // 0..1
    const int wn = warp & 3;    // 0..3
    const int bm = blockIdx.y * 128;
    const int bn = blockIdx.x * 128;

    float acc[4][4][4];
#pragma unroll
    for (int i = 0; i < 4; i++)
#pragma unroll
        for (int j = 0; j < 4; j++)
#pragma unroll
            for (int v = 0; v < 4; v++) acc[i][j][v] = 0.f;

    const int ar = tid >> 3;          // 0..31 (row step 32)
    const int ac = (tid & 7) << 2;    // 0..28
    const int br = tid >> 5;          // 0..7  (row step 8)
    const int bc = lane << 2;         // 0..124

    for (int k0 = 0; k0 < K; k0 += 32) {
#pragma unroll
        for (int p = 0; p < 4; p++) {
            int r = ar + p * 32;
            float4 v = *reinterpret_cast<const float4*>(A + (size_t)(bm + r) * K + k0 + ac);
            uint4 h, l;
            tf32_split(v.x, h.x, l.x); tf32_split(v.y, h.y, l.y);
            tf32_split(v.z, h.z, l.z); tf32_split(v.w, h.w, l.w);
            *reinterpret_cast<uint4*>(&Ah[r * 36 + ac]) = h;
            *reinterpret_cast<uint4*>(&Al[r * 36 + ac]) = l;
        }
#pragma unroll
        for (int p = 0; p < 4; p++) {
            int r = br + p * 8;
            float4 v = *reinterpret_cast<const float4*>(B + (size_t)(k0 + r) * N + bn + bc);
            uint4 h, l;
            tf32_split(v.x, h.x, l.x); tf32_split(v.y, h.y, l.y);
            tf32_split(v.z, h.z, l.z); tf32_split(v.w, h.w, l.w);
            *reinterpret_cast<uint4*>(&Bh[r * 136 + bc]) = h;
            *reinterpret_cast<uint4*>(&Bl[r * 136 + bc]) = l;
        }
        __syncthreads();

#pragma unroll
        for (int ks = 0; ks < 4; ks++) {
            const int kb = ks * 8;
            uint32_t afh[4][4], afl[4][4], bfh[4][2], bfl[4][2];
#pragma unroll
            for (int mt = 0; mt < 4; mt++) {
                int r0 = wm * 64 + mt * 16;
                int i0 = (r0 + g) * 36 + kb + t;
                int i1 = (r0 + 8 + g) * 36 + kb + t;
                afh[mt][0] = Ah[i0];     afl[mt][0] = Al[i0];
                afh[mt][1] = Ah[i1];     afl[mt][1] = Al[i1];
                afh[mt][2] = Ah[i0 + 4]; afl[mt][2] = Al[i0 + 4];
                afh[mt][3] = Ah[i1 + 4]; afl[mt][3] = Al[i1 + 4];
            }
#pragma unroll
            for (int nt = 0; nt < 4; nt++) {
                int c0 = wn * 32 + nt * 8;
                int i0 = (kb + t) * 136 + c0 + g;
                int i1 = (kb + t + 4) * 136 + c0 + g;
                bfh[nt][0] = Bh[i0]; bfl[nt][0] = Bl[i0];
                bfh[nt][1] = Bh[i1]; bfl[nt][1] = Bl[i1];
            }
#pragma unroll
            for (int mt = 0; mt < 4; mt++)
#pragma unroll
                for (int nt = 0; nt < 4; nt++)
                    mma3(acc[mt][nt], afh[mt], afl[mt], bfh[nt], bfl[nt]);
        }
        __syncthreads();
    }

#pragma unroll
    for (int mt = 0; mt < 4; mt++) {
        int row = bm + wm * 64 + mt * 16 + g;
#pragma unroll
        for (int nt = 0; nt < 4; nt++) {
            int col = bn + wn * 32 + nt * 8 + 2 * t;
            *reinterpret_cast<float2*>(C + (size_t)row * N + col) =
                make_float2(acc[mt][nt][0], acc[mt][nt][1]);
            *reinterpret_cast<float2*>(C + (size_t)(row + 8) * N + col) =
                make_float2(acc[mt][nt][2], acc[mt][nt][3]);
        }
    }
}

// ---------------------------------------------------------------------------
// 3xTF32 MMA flash attention. Block = 128 threads (4 warps), 64 q-rows.
// Dynamic smem: Ks/Vs/Ps each hi+lo, [64][68] u32.
// NOTE: reference MULTIPLIES logits by sqrt(64)=8.
// ---------------------------------------------------------------------------
#define FT (64 * 68)
#define FLASH_SMEM (6 * FT * 4)

__global__ void __launch_bounds__(128, 2)
flash_3xtf32_kernel(const float* __restrict__ Q, const float* __restrict__ KV,
                    float* __restrict__ O) {
    extern __shared__ uint32_t sm[];
    uint32_t* Kh = sm;
    uint32_t* Kl = sm + FT;
    uint32_t* Vh = sm + 2 * FT;
    uint32_t* Vl = sm + 3 * FT;
    uint32_t* Ph = sm + 4 * FT;
    uint32_t* Pl = sm + 5 * FT;

    const int tid  = threadIdx.x;
    const int lane = tid & 31;
    const int warp = tid >> 5;
    const int g = lane >> 2;
    const int t = lane & 3;
    const int wr = warp * 16;

    const int b  = blockIdx.z;
    const int h  = blockIdx.y;
    const int q0 = blockIdx.x * 64;

    // ---- stage Q tile 64x64 fp32 bits into Ph, then split into register frags ----
#pragma unroll
    for (int p = 0; p < 8; p++) {
        int idx = tid + p * 128;
        int r = idx >> 4;
        int c = (idx & 15) << 2;
        float4 v = *reinterpret_cast<const float4*>(
            Q + (size_t)(b * 2048 + q0 + r) * 1024 + h * 64 + c);
        *reinterpret_cast<float4*>(reinterpret_cast<float*>(Ph) + r * 68 + c) = v;
    }
    __syncthreads();

    uint32_t qh[8][4], ql[8][4];
#pragma unroll
    for (int ks = 0; ks < 8; ks++) {
        int kb = ks * 8;
        const float* Pf = reinterpret_cast<const float*>(Ph);
        tf32_split(Pf[(wr + g) * 68 + kb + t],         qh[ks][0], ql[ks][0]);
        tf32_split(Pf[(wr + 8 + g) * 68 + kb + t],     qh[ks][1], ql[ks][1]);
        tf32_split(Pf[(wr + g) * 68 + kb + t + 4],     qh[ks][2], ql[ks][2]);
        tf32_split(Pf[(wr + 8 + g) * 68 + kb + t + 4], qh[ks][3], ql[ks][3]);
    }
    __syncthreads();

    float of[8][4];
#pragma unroll
    for (int i = 0; i < 8; i++)
#pragma unroll
        for (int v = 0; v < 4; v++) of[i][v] = 0.f;
    float m0 = -1e30f, m1 = -1e30f, l0 = 0.f, l1 = 0.f;

    const float* Kb = KV + (size_t)b * 2048 * 2048 + h * 64;

    for (int j0 = 0; j0 < 2048; j0 += 64) {
        // ---- load + split K,V tiles ----
#pragma unroll
        for (int p = 0; p < 8; p++) {
            int idx = tid + p * 128;
            int r = idx >> 4;
            int c = (idx & 15) << 2;
            const float* kp = Kb + (size_t)(j0 + r) * 2048 + c;
            float4 kv4 = *reinterpret_cast<const float4*>(kp);
            uint4 hh, ll;
            tf32_split(kv4.x, hh.x, ll.x); tf32_split(kv4.y, hh.y, ll.y);
            tf32_split(kv4.z, hh.z, ll.z); tf32_split(kv4.w, hh.w, ll.w);
            *reinterpret_cast<uint4*>(&Kh[r * 68 + c]) = hh;
            *reinterpret_cast<uint4*>(&Kl[r * 68 + c]) = ll;
            float4 vv4 = *reinterpret_cast<const float4*>(kp + 1024);
            tf32_split(vv4.x, hh.x, ll.x); tf32_split(vv4.y, hh.y, ll.y);
            tf32_split(vv4.z, hh.z, ll.z); tf32_split(vv4.w, hh.w, ll.w);
            *reinterpret_cast<uint4*>(&Vh[r * 68 + c]) = hh;
            *reinterpret_cast<uint4*>(&Vl[r * 68 + c]) = ll;
        }
        __syncthreads();

        // ---- S = Q K^T (3xTF32) ----
        float sf[8][4];
#pragma unroll
        for (int nt = 0; nt < 8; nt++)
#pragma unroll
            for (int v = 0; v < 4; v++) sf[nt][v] = 0.f;

#pragma unroll
        for (int ks = 0; ks < 8; ks++) {
            int kb = ks * 8;
#pragma unroll
            for (int nt = 0; nt < 8; nt++) {
                int i0 = (nt * 8 + g) * 68 + kb + t;
                uint32_t bh[2] = { Kh[i0], Kh[i0 + 4] };
                uint32_t bl[2] = { Kl[i0], Kl[i0 + 4] };
                mma3(sf[nt], qh[ks], ql[ks], bh, bl);
            }
        }

        // ---- online softmax (x8 scale; rows g and g+8) ----
        float r0m = -1e30f, r1m = -1e30f;
#pragma unroll
        for (int nt = 0; nt < 8; nt++) {
            sf[nt][0] *= 8.f; sf[nt][1] *= 8.f; sf[nt][2] *= 8.f; sf[nt][3] *= 8.f;
            r0m = fmaxf(r0m, fmaxf(sf[nt][0], sf[nt][1]));
            r1m = fmaxf(r1m, fmaxf(sf[nt][2], sf[nt][3]));
        }
        r0m = fmaxf(r0m, __shfl_xor_sync(0xffffffffu, r0m, 1));
        r0m = fmaxf(r0m, __shfl_xor_sync(0xffffffffu, r0m, 2));
        r1m = fmaxf(r1m, __shfl_xor_sync(0xffffffffu, r1m, 1));
        r1m = fmaxf(r1m, __shfl_xor_sync(0xffffffffu, r1m, 2));

        float mn0 = fmaxf(m0, r0m), mn1 = fmaxf(m1, r1m);
        float cr0 = __expf(m0 - mn0), cr1 = __expf(m1 - mn1);
        float s0 = 0.f, s1 = 0.f;
#pragma unroll
        for (int nt = 0; nt < 8; nt++) {
            sf[nt][0] = __expf(sf[nt][0] - mn0);
            sf[nt][1] = __expf(sf[nt][1] - mn0);
            sf[nt][2] = __expf(sf[nt][2] - mn1);
            sf[nt][3] = __expf(sf[nt][3] - mn1);
            s0 += sf[nt][0] + sf[nt][1];
            s1 += sf[nt][2] + sf[nt][3];
        }
        s0 += __shfl_xor_sync(0xffffffffu, s0, 1);
        s0 += __shfl_xor_sync(0xffffffffu, s0, 2);
        s1 += __shfl_xor_sync(0xffffffffu, s1, 1);
        s1 += __shfl_xor_sync(0xffffffffu, s1, 2);
        l0 = l0 * cr0 + s0;  m0 = mn0;
        l1 = l1 * cr1 + s1;  m1 = mn1;
#pragma unroll
        for (int dt = 0; dt < 8; dt++) {
            of[dt][0] *= cr0; of[dt][1] *= cr0;
            of[dt][2] *= cr1; of[dt][3] *= cr1;
        }

        // ---- stage P hi/lo into per-warp-private rows ----
#pragma unroll
        for (int nt = 0; nt < 8; nt++) {
            int jc = nt * 8 + 2 * t;
            uint32_t hh, ll;
            tf32_split(sf[nt][0], hh, ll);
            Ph[(wr + g) * 68 + jc] = hh;      Pl[(wr + g) * 68 + jc] = ll;
            tf32_split(sf[nt][1], hh, ll);
            Ph[(wr + g) * 68 + jc + 1] = hh;  Pl[(wr + g) * 68 + jc + 1] = ll;
            tf32_split(sf[nt][2], hh, ll);
            Ph[(wr + 8 + g) * 68 + jc] = hh;      Pl[(wr + 8 + g) * 68 + jc] = ll;
            tf32_split(sf[nt][3], hh, ll);
            Ph[(wr + 8 + g) * 68 + jc + 1] = hh;  Pl[(wr + 8 + g) * 68 + jc + 1] = ll;
        }
        __syncwarp();

        // ---- O += P V (3xTF32) ----
#pragma unroll
        for (int ks = 0; ks < 8; ks++) {
            int kb = ks * 8;
            int i0 = (wr + g) * 68 + kb + t;
            int i1 = (wr + 8 + g) * 68 + kb + t;
            uint32_t ah[4] = { Ph[i0], Ph[i1], Ph[i0 + 4], Ph[i1 + 4] };
            uint32_t al[4] = { Pl[i0], Pl[i1], Pl[i0 + 4], Pl[i1 + 4] };
#pragma unroll
            for (int nt = 0; nt < 8; nt++) {
                int j0i = (kb + t) * 68 + nt * 8 + g;
                int j1i = (kb + t + 4) * 68 + nt * 8 + g;
                uint32_t bh[2] = { Vh[j0i], Vh[j1i] };
                uint32_t bl[2] = { Vl[j0i], Vl[j1i] };
                mma3(of[nt], ah, al, bh, bl);
            }
        }
        __syncthreads();   // before K/V overwrite
    }

    float inv0 = 1.f / l0, inv1 = 1.f / l1;
    int row0 = b * 2048 + q0 + wr + g;
#pragma unroll
    for (int nt = 0; nt < 8; nt++) {
        int col = h * 64 + nt * 8 + 2 * t;
        *reinterpret_cast<float2*>(O + (size_t)row0 * 1024 + col) =
            make_float2(of[nt][0] * inv0, of[nt][1] * inv0);
        *reinterpret_cast<float2*>(O + (size_t)(row0 + 8) * 1024 + col) =
            make_float2(of[nt][2] * inv1, of[nt][3] * inv1);
    }
}

// ---------------------------------------------------------------------------
extern "C" void kernel_launch(void* const* d_in, const int* in_sizes, int n_in,
                              void* d_out, int out_size) {
    const float* x     = (const float*)d_in[0];   // [2,2048,1024]
    const float* w_q   = (const float*)d_in[1];   // [1024,1024]
    const float* w_vk  = (const float*)d_in[2];   // [1024,2048]
    const float* w_out = (const float*)d_in[3];   // [1024,1024]
    float* out = (float*)d_out;                   // [2,2048,1024]

    float *q, *kv, *ao;
    cudaGetSymbolAddress((void**)&q,  g_q);
    cudaGetSymbolAddress((void**)&kv, g_kv);
    cudaGetSymbolAddress((void**)&ao, g_ao);

    static bool attr_done = false;
    if (!attr_done) {
        cudaFuncSetAttribute(gemm_3xtf32_kernel,
                             cudaFuncAttributeMaxDynamicSharedMemorySize, GEMM_SMEM);
        cudaFuncSetAttribute(flash_3xtf32_kernel,
                             cudaFuncAttributeMaxDynamicSharedMemorySize, FLASH_SMEM);
        attr_done = true;
    }

    gemm_3xtf32_kernel<<<dim3(8, 32), 256, GEMM_SMEM>>>(x, w_q, q, 4096, 1024, 1024);
    gemm_3xtf32_kernel<<<dim3(16, 32), 256, GEMM_SMEM>>>(x, w_vk, kv, 4096, 2048, 1024);
    flash_3xtf32_kernel<<<dim3(32, 16, 2), 128, FLASH_SMEM>>>(q, kv, ao);
    gemm_3xtf32_kernel<<<dim3(8, 32), 256, GEMM_SMEM>>>(ao, w_out, out, 4096, 1024, 1024);
}